// round 1
// baseline (speedup 1.0000x reference)
#include <cuda_runtime.h>
#include <cstddef>

// Problem constants (fixed by reference)
#define Vn 100000
#define Kn 64
#define Fn 16
#define VPB 8            // vertices per covariance block
#define TM 128           // MLP rows per block
#define PITCH 132        // padded row pitch for activation buffers (floats, 16B-multiple)

static const int R_ROWS = Vn * Fn;        // 1,600,000 MLP rows
#define EPSc 1e-4f

// Scratch: cov rows [V*F, 9]  (57.6 MB, static device allocation — allowed)
__device__ float g_cov[(size_t)Vn * Fn * 9];

// ---------------------------------------------------------------------------
// Kernel A: weighted neighbour covariance
// grid: V/VPB blocks of 128 threads.
//   stage 1: 128 threads stage idx / exp(-10*d2) / neighbour coords for 8 vertices
//   stage 2: thread = (local vertex, feature) accumulates ws, mean, 2nd moments
// ---------------------------------------------------------------------------
__global__ void __launch_bounds__(128) cov_kernel(
    const float* __restrict__ coords,
    const float* __restrict__ distsq,
    const float* __restrict__ feats,
    const int*   __restrict__ nidx)
{
    __shared__ int   s_idx[VPB * Kn];
    __shared__ float s_ex [VPB * Kn];
    __shared__ float s_nbc[VPB * Kn * 3];

    const int v0 = blockIdx.x * VPB;

    for (int p = threadIdx.x; p < VPB * Kn; p += 128) {
        const int v  = v0 + (p >> 6);
        const int kk = p & 63;
        const int idx = nidx[v * Kn + kk];
        s_idx[p] = idx;
        s_ex[p]  = __expf(-10.0f * distsq[v * Kn + kk]);
        s_nbc[p * 3 + 0] = coords[idx * 3 + 0];
        s_nbc[p * 3 + 1] = coords[idx * 3 + 1];
        s_nbc[p * 3 + 2] = coords[idx * 3 + 2];
    }
    __syncthreads();

    const int lv = threadIdx.x >> 4;   // local vertex 0..7
    const int f  = threadIdx.x & 15;   // feature 0..15
    const int base = lv * Kn;

    float ws = 0.f;
    float m0 = 0.f, m1 = 0.f, m2 = 0.f;
    float q00 = 0.f, q01 = 0.f, q02 = 0.f, q11 = 0.f, q12 = 0.f, q22 = 0.f;

    #pragma unroll 4
    for (int kk = 0; kk < Kn; kk++) {
        const int idx = s_idx[base + kk];
        const float w = __ldg(&feats[idx * Fn + f]) * s_ex[base + kk];
        const float x = s_nbc[(base + kk) * 3 + 0];
        const float y = s_nbc[(base + kk) * 3 + 1];
        const float z = s_nbc[(base + kk) * 3 + 2];
        ws += w;
        m0 = fmaf(w, x, m0); m1 = fmaf(w, y, m1); m2 = fmaf(w, z, m2);
        const float wx = w * x, wy = w * y, wz = w * z;
        q00 = fmaf(wx, x, q00); q01 = fmaf(wx, y, q01); q02 = fmaf(wx, z, q02);
        q11 = fmaf(wy, y, q11); q12 = fmaf(wy, z, q12); q22 = fmaf(wz, z, q22);
    }

    const float inv = 1.0f / (ws + EPSc);
    const float mu0 = m0 * inv, mu1 = m1 * inv, mu2 = m2 * inv;
    const float c0 = q00 * inv - mu0 * mu0;
    const float c1 = q01 * inv - mu0 * mu1;
    const float c2 = q02 * inv - mu0 * mu2;
    const float c4 = q11 * inv - mu1 * mu1;
    const float c5 = q12 * inv - mu1 * mu2;
    const float c8 = q22 * inv - mu2 * mu2;

    float* o = g_cov + ((size_t)(v0 + lv) * Fn + f) * 9;
    o[0] = c0; o[1] = c1; o[2] = c2;
    o[3] = c1; o[4] = c4; o[5] = c5;
    o[6] = c2; o[7] = c5; o[8] = c8;
}

// ---------------------------------------------------------------------------
// Kernel B: fused 4-layer MLP (9 -> 64 -> 64 -> 64 -> 9, ELU after every layer)
// 256 threads, 128 rows per block. Weights + ping-pong activations in SMEM.
// Micro-tile per thread: 8 rows x 4 cols. Activations stored k-major [k][row].
// ---------------------------------------------------------------------------
__device__ __forceinline__ float elu_fast(float x) {
    return x > 0.f ? x : (__expf(x) - 1.0f);
}

template <int KD>
__device__ __forceinline__ void layer_tile(
    const float* __restrict__ in, float* __restrict__ outb,
    const float* __restrict__ Wsh, const float* __restrict__ bsh,
    int tx, int ty)
{
    float acc[4][8];
    #pragma unroll
    for (int j = 0; j < 4; j++)
        #pragma unroll
        for (int r = 0; r < 8; r++) acc[j][r] = 0.f;

    #pragma unroll 8
    for (int k = 0; k < KD; k++) {
        const float4 w  = *reinterpret_cast<const float4*>(&Wsh[k * 64 + tx * 4]);
        const float4 a0 = *reinterpret_cast<const float4*>(&in[k * PITCH + ty * 8]);
        const float4 a1 = *reinterpret_cast<const float4*>(&in[k * PITCH + ty * 8 + 4]);
        const float av[8] = {a0.x, a0.y, a0.z, a0.w, a1.x, a1.y, a1.z, a1.w};
        const float wv[4] = {w.x, w.y, w.z, w.w};
        #pragma unroll
        for (int j = 0; j < 4; j++)
            #pragma unroll
            for (int r = 0; r < 8; r++)
                acc[j][r] = fmaf(wv[j], av[r], acc[j][r]);
    }

    #pragma unroll
    for (int j = 0; j < 4; j++) {
        const float bj = bsh[tx * 4 + j];
        float o[8];
        #pragma unroll
        for (int r = 0; r < 8; r++) o[r] = elu_fast(acc[j][r] + bj);
        *reinterpret_cast<float4*>(&outb[(tx * 4 + j) * PITCH + ty * 8]) =
            make_float4(o[0], o[1], o[2], o[3]);
        *reinterpret_cast<float4*>(&outb[(tx * 4 + j) * PITCH + ty * 8 + 4]) =
            make_float4(o[4], o[5], o[6], o[7]);
    }
}

// SMEM layout (floats):
//   sW1[4096] sW2[4096] sW0[576] sW3[576] b0[64] b1[64] b2[64] b3pad[16]
//   bufA[64*PITCH] bufB[64*PITCH]
#define SMEM_FLOATS (4096 + 4096 + 576 + 576 + 64 + 64 + 64 + 16 + 2 * 64 * PITCH)
#define SMEM_BYTES (SMEM_FLOATS * 4)

__global__ void __launch_bounds__(256) mlp_kernel(
    const float* __restrict__ W0, const float* __restrict__ b0,
    const float* __restrict__ W1, const float* __restrict__ b1,
    const float* __restrict__ W2, const float* __restrict__ b2,
    const float* __restrict__ W3, const float* __restrict__ b3,
    float* __restrict__ out)
{
    extern __shared__ float sm[];
    float* sW1 = sm;
    float* sW2 = sW1 + 4096;
    float* sW0 = sW2 + 4096;   // [9][64]
    float* sW3 = sW0 + 576;    // [64][9]
    float* sB0 = sW3 + 576;
    float* sB1 = sB0 + 64;
    float* sB2 = sB1 + 64;
    float* sB3 = sB2 + 64;     // 9 used, padded to 16
    float* bufA = sB3 + 16;
    float* bufB = bufA + 64 * PITCH;

    const int tid = threadIdx.x;

    for (int i = tid; i < 4096; i += 256) { sW1[i] = W1[i]; sW2[i] = W2[i]; }
    for (int i = tid; i < 576;  i += 256) { sW0[i] = W0[i]; sW3[i] = W3[i]; }
    if (tid < 64) { sB0[tid] = b0[tid]; sB1[tid] = b1[tid]; sB2[tid] = b2[tid]; }
    if (tid < 9)  { sB3[tid] = b3[tid]; }

    // Load input tile: cov rows -> bufA as [k][row] (k = 0..8)
    const size_t r0 = (size_t)blockIdx.x * TM;
    const float* src = g_cov + r0 * 9;
    for (int p = tid; p < TM * 9; p += 256) {
        const int r  = p / 9;
        const int kk = p - r * 9;
        bufA[kk * PITCH + r] = src[p];
    }
    __syncthreads();

    const int tx = tid & 15;   // col group (4 cols each)
    const int ty = tid >> 4;   // row group (8 rows each)

    layer_tile<9>(bufA, bufB, sW0, sB0, tx, ty);
    __syncthreads();
    layer_tile<64>(bufB, bufA, sW1, sB1, tx, ty);
    __syncthreads();
    layer_tile<64>(bufA, bufB, sW2, sB2, tx, ty);
    __syncthreads();

    // Final layer: 64 -> 9, ELU (accurate expm1), write straight to output
    float* dst = out + r0 * 9;
    for (int p = tid; p < TM * 9; p += 256) {
        const int r = p / 9;
        const int j = p - r * 9;
        float acc = sB3[j];
        #pragma unroll 8
        for (int k = 0; k < 64; k++)
            acc = fmaf(bufB[k * PITCH + r], sW3[k * 9 + j], acc);
        dst[p] = acc > 0.f ? acc : expm1f(acc);
    }
}

// ---------------------------------------------------------------------------
// Launch
// ---------------------------------------------------------------------------
extern "C" void kernel_launch(void* const* d_in, const int* in_sizes, int n_in,
                              void* d_out, int out_size)
{
    const float* coords = (const float*)d_in[0];
    const float* distsq = (const float*)d_in[1];
    const float* feats  = (const float*)d_in[2];
    const int*   nidx   = (const int*)  d_in[3];
    const float* W0 = (const float*)d_in[4];
    const float* b0 = (const float*)d_in[5];
    const float* W1 = (const float*)d_in[6];
    const float* b1 = (const float*)d_in[7];
    const float* W2 = (const float*)d_in[8];
    const float* b2 = (const float*)d_in[9];
    const float* W3 = (const float*)d_in[10];
    const float* b3 = (const float*)d_in[11];
    float* out = (float*)d_out;

    cov_kernel<<<Vn / VPB, 128>>>(coords, distsq, feats, nidx);

    cudaFuncSetAttribute(mlp_kernel,
                         cudaFuncAttributeMaxDynamicSharedMemorySize, SMEM_BYTES);
    mlp_kernel<<<R_ROWS / TM, 256, SMEM_BYTES>>>(W0, b0, W1, b1, W2, b2, W3, b3, out);
}

// round 2
// speedup vs baseline: 1.0187x; 1.0187x over previous
#include <cuda_runtime.h>
#include <cstddef>

// Problem constants (fixed by reference)
#define Vn 100000
#define Kn 64
#define Fn 16
#define VPB 8            // vertices per covariance block
#define TM 128           // MLP rows per block
#define PITCH 132        // floats per activation column (128 rows + pad) = 33 float4 chunks

static const int R_ROWS = Vn * Fn;        // 1,600,000 MLP rows
#define EPSc 1e-4f

// Scratch: cov rows [V*F, 9]  (57.6 MB, static device allocation — allowed)
__device__ float g_cov[(size_t)Vn * Fn * 9];

// ---------------------------------------------------------------------------
// Kernel A: weighted neighbour covariance (unchanged from round 1)
// ---------------------------------------------------------------------------
__global__ void __launch_bounds__(128) cov_kernel(
    const float* __restrict__ coords,
    const float* __restrict__ distsq,
    const float* __restrict__ feats,
    const int*   __restrict__ nidx)
{
    __shared__ int   s_idx[VPB * Kn];
    __shared__ float s_ex [VPB * Kn];
    __shared__ float s_nbc[VPB * Kn * 3];

    const int v0 = blockIdx.x * VPB;

    for (int p = threadIdx.x; p < VPB * Kn; p += 128) {
        const int v  = v0 + (p >> 6);
        const int kk = p & 63;
        const int idx = nidx[v * Kn + kk];
        s_idx[p] = idx;
        s_ex[p]  = __expf(-10.0f * distsq[v * Kn + kk]);
        s_nbc[p * 3 + 0] = coords[idx * 3 + 0];
        s_nbc[p * 3 + 1] = coords[idx * 3 + 1];
        s_nbc[p * 3 + 2] = coords[idx * 3 + 2];
    }
    __syncthreads();

    const int lv = threadIdx.x >> 4;
    const int f  = threadIdx.x & 15;
    const int base = lv * Kn;

    float ws = 0.f;
    float m0 = 0.f, m1 = 0.f, m2 = 0.f;
    float q00 = 0.f, q01 = 0.f, q02 = 0.f, q11 = 0.f, q12 = 0.f, q22 = 0.f;

    #pragma unroll 4
    for (int kk = 0; kk < Kn; kk++) {
        const int idx = s_idx[base + kk];
        const float w = __ldg(&feats[idx * Fn + f]) * s_ex[base + kk];
        const float x = s_nbc[(base + kk) * 3 + 0];
        const float y = s_nbc[(base + kk) * 3 + 1];
        const float z = s_nbc[(base + kk) * 3 + 2];
        ws += w;
        m0 = fmaf(w, x, m0); m1 = fmaf(w, y, m1); m2 = fmaf(w, z, m2);
        const float wx = w * x, wy = w * y, wz = w * z;
        q00 = fmaf(wx, x, q00); q01 = fmaf(wx, y, q01); q02 = fmaf(wx, z, q02);
        q11 = fmaf(wy, y, q11); q12 = fmaf(wy, z, q12); q22 = fmaf(wz, z, q22);
    }

    const float inv = 1.0f / (ws + EPSc);
    const float mu0 = m0 * inv, mu1 = m1 * inv, mu2 = m2 * inv;
    const float c0 = q00 * inv - mu0 * mu0;
    const float c1 = q01 * inv - mu0 * mu1;
    const float c2 = q02 * inv - mu0 * mu2;
    const float c4 = q11 * inv - mu1 * mu1;
    const float c5 = q12 * inv - mu1 * mu2;
    const float c8 = q22 * inv - mu2 * mu2;

    float* o = g_cov + ((size_t)(v0 + lv) * Fn + f) * 9;
    o[0] = c0; o[1] = c1; o[2] = c2;
    o[3] = c1; o[4] = c4; o[5] = c5;
    o[6] = c2; o[7] = c5; o[8] = c8;
}

// ---------------------------------------------------------------------------
// Kernel B v2: fused 4-layer MLP, 8x8 register tiles, conflict-free smem.
//
// Activation layout (k-major, XOR-chunk-swizzled):
//   element (row r, col k) lives at buf[k*PITCH + 4*((r>>2) ^ ((k>>3)&7)) + (r&3)]
//   -> epilogue float4 stores hit the 4-wavefront floor, loads are 1 wavefront.
//
// Weight layout (chunk-permuted [k][64]):
//   orig col j: chunk c=j>>2 stored at slot ((c&1)*8 + (c>>1)).
//   -> thread tx reads slot tx (cols 8tx..8tx+3) and slot 8+tx (cols 8tx+4..+7);
//      each warp LDS.128 reads one contiguous 128B span = 1 wavefront.
// ---------------------------------------------------------------------------

template<int KD>
__device__ __forceinline__ void tile_layer(
    const float* __restrict__ in, float* __restrict__ outb,
    const float4* __restrict__ Wp, const float* __restrict__ bias,
    int tx, int ty)
{
    float acc[8][8];
    #pragma unroll
    for (int j = 0; j < 8; j++)
        #pragma unroll
        for (int r = 0; r < 8; r++) acc[j][r] = 0.f;

    #pragma unroll 8
    for (int k = 0; k < KD; k++) {
        const int key = (k >> 3) & 7;
        const float4* arow = (const float4*)(in + k * PITCH);
        const float4 a0 = arow[(2 * ty) ^ key];
        const float4 a1 = arow[(2 * ty + 1) ^ key];
        const float4 w0 = Wp[k * 16 + tx];
        const float4 w1 = Wp[k * 16 + 8 + tx];
        const float av[8] = {a0.x, a0.y, a0.z, a0.w, a1.x, a1.y, a1.z, a1.w};
        const float wv[8] = {w0.x, w0.y, w0.z, w0.w, w1.x, w1.y, w1.z, w1.w};
        #pragma unroll
        for (int j = 0; j < 8; j++)
            #pragma unroll
            for (int r = 0; r < 8; r++)
                acc[j][r] = fmaf(wv[j], av[r], acc[j][r]);
    }

    #pragma unroll
    for (int j = 0; j < 8; j++) {
        const int col = tx * 8 + j;
        const float b = bias[col];
        float o[8];
        #pragma unroll
        for (int r = 0; r < 8; r++) {
            const float t = acc[j][r] + b;
            o[r] = t > 0.f ? t : (__expf(t) - 1.0f);   // ELU
        }
        float4* orow = (float4*)(outb + col * PITCH);
        orow[(2 * ty) ^ tx]     = make_float4(o[0], o[1], o[2], o[3]);
        orow[(2 * ty + 1) ^ tx] = make_float4(o[4], o[5], o[6], o[7]);
    }
}

// SMEM floats: W1P[4096] W2P[4096] W0P[576] W3T[576] B0[64] B1[64] B2[64] B3[16]
//              bufA[64*PITCH] bufB[64*PITCH]
#define SMEM_FLOATS (4096 + 4096 + 576 + 576 + 64 + 64 + 64 + 16 + 2 * 64 * PITCH)
#define SMEM_BYTES (SMEM_FLOATS * 4)

__global__ void __launch_bounds__(128, 2) mlp_kernel(
    const float* __restrict__ W0, const float* __restrict__ b0,
    const float* __restrict__ W1, const float* __restrict__ b1,
    const float* __restrict__ W2, const float* __restrict__ b2,
    const float* __restrict__ W3, const float* __restrict__ b3,
    float* __restrict__ out)
{
    extern __shared__ float sm[];
    float* sW1P = sm;
    float* sW2P = sW1P + 4096;
    float* sW0P = sW2P + 4096;   // [9][64] permuted
    float* sW3T = sW0P + 576;    // [9][64]  (W3T[j*64+k] = W3[k*9+j])
    float* sB0  = sW3T + 576;
    float* sB1  = sB0 + 64;
    float* sB2  = sB1 + 64;
    float* sB3  = sB2 + 64;      // 9 used, padded to 16
    float* bufA = sB3 + 16;
    float* bufB = bufA + 64 * PITCH;

    const int tid = threadIdx.x;
    const int tx = tid & 7;
    const int ty = tid >> 3;

    // Stage + permute weights (reads coalesced, smem scatter one-time)
    for (int s = tid; s < 4096; s += 128) {
        const int k = s >> 6, j = s & 63;
        const int c = j >> 2, m = j & 3;
        const int np = (((c & 1) << 3) + (c >> 1)) * 4 + m;
        sW1P[k * 64 + np] = W1[s];
        sW2P[k * 64 + np] = W2[s];
    }
    for (int s = tid; s < 576; s += 128) {
        // W0 is [9][64]
        const int k = s >> 6, j = s & 63;
        const int c = j >> 2, m = j & 3;
        const int np = (((c & 1) << 3) + (c >> 1)) * 4 + m;
        sW0P[k * 64 + np] = W0[s];
        // W3 is [64][9] -> transpose
        const int k3 = s / 9, j3 = s - k3 * 9;
        sW3T[j3 * 64 + k3] = W3[s];
    }
    if (tid < 64) { sB0[tid] = b0[tid]; sB1[tid] = b1[tid]; sB2[tid] = b2[tid]; }
    if (tid < 9)  { sB3[tid] = b3[tid]; }

    // Stage input tile: cov rows -> bufA (k-major, swizzled)
    const size_t r0 = (size_t)blockIdx.x * TM;
    const float* src = g_cov + r0 * 9;
    for (int p = tid; p < TM * 9; p += 128) {
        const int r = p / 9;
        const int k = p - r * 9;
        const int key = k >> 3;
        bufA[k * PITCH + ((((r >> 2) ^ key) << 2) | (r & 3))] = src[p];
    }
    __syncthreads();

    tile_layer<9>(bufA, bufB, (const float4*)sW0P, sB0, tx, ty);
    __syncthreads();
    tile_layer<64>(bufB, bufA, (const float4*)sW1P, sB1, tx, ty);
    __syncthreads();
    tile_layer<64>(bufA, bufB, (const float4*)sW2P, sB2, tx, ty);
    __syncthreads();

    // Final layer 64 -> 9: one thread per row, register-resident activations.
    {
        const int r = tid;
        float a[64];
        #pragma unroll 8
        for (int k = 0; k < 64; k++) {
            const int key = (k >> 3) & 7;
            a[k] = bufB[k * PITCH + ((((r >> 2) ^ key) << 2) | (r & 3))];
        }
        float* dst = out + (r0 + r) * 9;
        #pragma unroll
        for (int j = 0; j < 9; j++) {
            const float4* w = (const float4*)(sW3T + j * 64);
            float s = sB3[j];
            #pragma unroll
            for (int q = 0; q < 16; q++) {
                const float4 wq = w[q];
                s = fmaf(a[4 * q + 0], wq.x, s);
                s = fmaf(a[4 * q + 1], wq.y, s);
                s = fmaf(a[4 * q + 2], wq.z, s);
                s = fmaf(a[4 * q + 3], wq.w, s);
            }
            dst[j] = s > 0.f ? s : expm1f(s);   // accurate ELU on final output
        }
    }
}

// ---------------------------------------------------------------------------
// Launch
// ---------------------------------------------------------------------------
extern "C" void kernel_launch(void* const* d_in, const int* in_sizes, int n_in,
                              void* d_out, int out_size)
{
    const float* coords = (const float*)d_in[0];
    const float* distsq = (const float*)d_in[1];
    const float* feats  = (const float*)d_in[2];
    const int*   nidx   = (const int*)  d_in[3];
    const float* W0 = (const float*)d_in[4];
    const float* b0 = (const float*)d_in[5];
    const float* W1 = (const float*)d_in[6];
    const float* b1 = (const float*)d_in[7];
    const float* W2 = (const float*)d_in[8];
    const float* b2 = (const float*)d_in[9];
    const float* W3 = (const float*)d_in[10];
    const float* b3 = (const float*)d_in[11];
    float* out = (float*)d_out;

    cov_kernel<<<Vn / VPB, 128>>>(coords, distsq, feats, nidx);

    cudaFuncSetAttribute(mlp_kernel,
                         cudaFuncAttributeMaxDynamicSharedMemorySize, SMEM_BYTES);
    mlp_kernel<<<R_ROWS / TM, 128, SMEM_BYTES>>>(W0, b0, W1, b1, W2, b2, W3, b3, out);
}

// round 4
// speedup vs baseline: 2.1848x; 2.1447x over previous
#include <cuda_runtime.h>
#include <cuda_bf16.h>
#include <cstdint>
#include <cstddef>

// Problem constants
#define Vn 100000
#define Kn 64
#define Fn 16
#define VPB 8
#define EPSc 1e-4f

static const int R_ROWS = Vn * Fn;   // 1,600,000 MLP rows; 100,000 16-row tiles

// Scratch: cov rows [V*F, 9] (static device allocation — allowed)
__device__ float g_cov[(size_t)Vn * Fn * 9];

// ---------------------------------------------------------------------------
// Warp-MMA helpers (sm_80-era PTX: legal on plain sm_100)
// ---------------------------------------------------------------------------
__device__ __forceinline__ uint32_t smem_u32(const void* p) {
    uint32_t a;
    asm("{ .reg .u64 t; cvta.to.shared.u64 t, %1; cvt.u32.u64 %0, t; }"
        : "=r"(a) : "l"(p));
    return a;
}

__device__ __forceinline__ void mma_bf16(float* d, const uint32_t* a,
                                         uint32_t b0, uint32_t b1) {
    asm volatile(
        "mma.sync.aligned.m16n8k16.row.col.f32.bf16.bf16.f32 "
        "{%0,%1,%2,%3}, {%4,%5,%6,%7}, {%8,%9}, {%0,%1,%2,%3};"
        : "+f"(d[0]), "+f"(d[1]), "+f"(d[2]), "+f"(d[3])
        : "r"(a[0]), "r"(a[1]), "r"(a[2]), "r"(a[3]), "r"(b0), "r"(b1));
}

__device__ __forceinline__ void ldsm4(uint32_t* r, uint32_t addr) {
    asm volatile("ldmatrix.sync.aligned.m8n8.x4.shared.b16 {%0,%1,%2,%3}, [%4];"
                 : "=r"(r[0]), "=r"(r[1]), "=r"(r[2]), "=r"(r[3])
                 : "r"(addr) : "memory");
}

// pack (x0 -> low half, x1 -> high half) as bf16x2 hi + residual lo
__device__ __forceinline__ void split2(float x0, float x1, uint32_t& h, uint32_t& l) {
    uint32_t hp;
    asm("cvt.rn.bf16x2.f32 %0, %1, %2;" : "=r"(hp) : "f"(x1), "f"(x0));
    const float h0 = __uint_as_float(hp << 16);
    const float h1 = __uint_as_float(hp & 0xFFFF0000u);
    const float l0 = x0 - h0;
    const float l1 = x1 - h1;
    uint32_t lp;
    asm("cvt.rn.bf16x2.f32 %0, %1, %2;" : "=r"(lp) : "f"(l1), "f"(l0));
    h = hp; l = lp;
}

__device__ __forceinline__ float elu_fast(float x) {
    return x > 0.f ? x : (__expf(x) - 1.0f);
}

// ---------------------------------------------------------------------------
// Kernel A: weighted neighbour covariance (unchanged; ~100 us)
// ---------------------------------------------------------------------------
__global__ void __launch_bounds__(128) cov_kernel(
    const float* __restrict__ coords,
    const float* __restrict__ distsq,
    const float* __restrict__ feats,
    const int*   __restrict__ nidx)
{
    __shared__ int   s_idx[VPB * Kn];
    __shared__ float s_ex [VPB * Kn];
    __shared__ float s_nbc[VPB * Kn * 3];

    const int v0 = blockIdx.x * VPB;

    for (int p = threadIdx.x; p < VPB * Kn; p += 128) {
        const int v  = v0 + (p >> 6);
        const int kk = p & 63;
        const int idx = nidx[v * Kn + kk];
        s_idx[p] = idx;
        s_ex[p]  = __expf(-10.0f * distsq[v * Kn + kk]);
        s_nbc[p * 3 + 0] = coords[idx * 3 + 0];
        s_nbc[p * 3 + 1] = coords[idx * 3 + 1];
        s_nbc[p * 3 + 2] = coords[idx * 3 + 2];
    }
    __syncthreads();

    const int lv = threadIdx.x >> 4;
    const int f  = threadIdx.x & 15;
    const int base = lv * Kn;

    float ws = 0.f, m0 = 0.f, m1 = 0.f, m2 = 0.f;
    float q00 = 0.f, q01 = 0.f, q02 = 0.f, q11 = 0.f, q12 = 0.f, q22 = 0.f;

    #pragma unroll 4
    for (int kk = 0; kk < Kn; kk++) {
        const int idx = s_idx[base + kk];
        const float w = __ldg(&feats[idx * Fn + f]) * s_ex[base + kk];
        const float x = s_nbc[(base + kk) * 3 + 0];
        const float y = s_nbc[(base + kk) * 3 + 1];
        const float z = s_nbc[(base + kk) * 3 + 2];
        ws += w;
        m0 = fmaf(w, x, m0); m1 = fmaf(w, y, m1); m2 = fmaf(w, z, m2);
        const float wx = w * x, wy = w * y, wz = w * z;
        q00 = fmaf(wx, x, q00); q01 = fmaf(wx, y, q01); q02 = fmaf(wx, z, q02);
        q11 = fmaf(wy, y, q11); q12 = fmaf(wy, z, q12); q22 = fmaf(wz, z, q22);
    }

    const float inv = 1.0f / (ws + EPSc);
    const float mu0 = m0 * inv, mu1 = m1 * inv, mu2 = m2 * inv;
    const float c0 = q00 * inv - mu0 * mu0;
    const float c1 = q01 * inv - mu0 * mu1;
    const float c2 = q02 * inv - mu0 * mu2;
    const float c4 = q11 * inv - mu1 * mu1;
    const float c5 = q12 * inv - mu1 * mu2;
    const float c8 = q22 * inv - mu2 * mu2;

    float* o = g_cov + ((size_t)(v0 + lv) * Fn + f) * 9;
    o[0] = c0; o[1] = c1; o[2] = c2;
    o[3] = c1; o[4] = c4; o[5] = c5;
    o[6] = c2; o[7] = c5; o[8] = c8;
}

// ---------------------------------------------------------------------------
// Kernel B v4: warp-level bf16-split tensor-core MLP.
// Each warp = one 16-row tile, activations register-resident between layers
// (D fragment of m16n8 pair == A fragment of m16k16).
// Weights: W^T in SMEM as bf16 hi/lo, pitch-padded for conflict-free LDSM.
//   Bt1/Bt2/Bt3 pitch 72 elems (144 B), Bt0 pitch 24 elems (48 B).
// ---------------------------------------------------------------------------
#define PB   72
#define PB0  24
#define OFF_B1H 0
#define OFF_B1L 9216
#define OFF_B2H 18432
#define OFF_B2L 27648
#define OFF_B0H 36864
#define OFF_B0L 39936
#define OFF_B3H 43008
#define OFF_B3L 45312
#define OFF_BIAS 47616          /* 208 floats */
#define OFF_AH  48448           /* 8 warps x 512 B */
#define OFF_AL  52544
#define MLP_SMEM 56640

__device__ __forceinline__ void put_hl(char* smc, int offH, int offL, int idx, float v) {
    const __nv_bfloat16 hb = __float2bfloat16_rn(v);
    const float lo = v - __bfloat162float(hb);
    ((__nv_bfloat16*)(smc + offH))[idx] = hb;
    ((__nv_bfloat16*)(smc + offL))[idx] = __float2bfloat16_rn(lo);
}

// One hidden-layer pass: d[32] += (AH+AL) x B(hi/lo), K=64, N=64.
__device__ __forceinline__ void hidden_layer(
    float* d, const uint32_t* AH, const uint32_t* AL,
    uint32_t sb, int offH, int offL, int lane)
{
    const int n    = (lane & 7) + ((lane >> 4) << 3);
    const int koff = ((lane >> 3) & 1) * 8;
    #pragma unroll
    for (int s = 0; s < 4; s++) {
        const uint32_t* ah = AH + 4 * s;
        const uint32_t* al = AL + 4 * s;
        #pragma unroll
        for (int ntp = 0; ntp < 4; ntp++) {
            const uint32_t ba = sb + ((n + ntp * 16) * PB + 16 * s + koff) * 2;
            uint32_t bh[4], bl[4];
            ldsm4(bh, ba + offH);
            ldsm4(bl, ba + offL);
            float* dp = d + ntp * 8;
            mma_bf16(dp, ah, bh[0], bh[1]);
            mma_bf16(dp, ah, bl[0], bl[1]);
            mma_bf16(dp, al, bh[0], bh[1]);
            mma_bf16(dp + 4, ah, bh[2], bh[3]);
            mma_bf16(dp + 4, ah, bl[2], bl[3]);
            mma_bf16(dp + 4, al, bh[2], bh[3]);
        }
    }
}

// Epilogue: bias + ELU on d[32] (64 cols), repack into next-layer A frags.
__device__ __forceinline__ void epi_repack(
    float* d, const float* bias, uint32_t* AH, uint32_t* AL, int lane)
{
    const int c = (lane & 3) * 2;
    #pragma unroll
    for (int t = 0; t < 8; t++) {
        const float bc0 = bias[8 * t + c];
        const float bc1 = bias[8 * t + c + 1];
        d[4 * t + 0] = elu_fast(d[4 * t + 0] + bc0);
        d[4 * t + 1] = elu_fast(d[4 * t + 1] + bc1);
        d[4 * t + 2] = elu_fast(d[4 * t + 2] + bc0);
        d[4 * t + 3] = elu_fast(d[4 * t + 3] + bc1);
    }
    #pragma unroll
    for (int s = 0; s < 4; s++) {
        split2(d[8 * s + 0], d[8 * s + 1], AH[4 * s + 0], AL[4 * s + 0]);
        split2(d[8 * s + 2], d[8 * s + 3], AH[4 * s + 1], AL[4 * s + 1]);
        split2(d[8 * s + 4], d[8 * s + 5], AH[4 * s + 2], AL[4 * s + 2]);
        split2(d[8 * s + 6], d[8 * s + 7], AH[4 * s + 3], AL[4 * s + 3]);
    }
}

__global__ void __launch_bounds__(256, 2) mlp_kernel(
    const float* __restrict__ W0, const float* __restrict__ b0,
    const float* __restrict__ W1, const float* __restrict__ b1,
    const float* __restrict__ W2, const float* __restrict__ b2,
    const float* __restrict__ W3, const float* __restrict__ b3,
    float* __restrict__ out)
{
    extern __shared__ char smc[];
    const uint32_t sb = smem_u32(smc);
    const int tid = threadIdx.x;
    const int lane = tid & 31;
    const int wid = tid >> 5;
    float* bias = (float*)(smc + OFF_BIAS);

    // ---- Stage weights (transposed, hi/lo split) + biases into SMEM ----
    for (int i = tid; i < 4096; i += 256) {
        const int n = i & 63, k = i >> 6;
        put_hl(smc, OFF_B1H, OFF_B1L, n * PB + k, W1[k * 64 + n]);
        put_hl(smc, OFF_B2H, OFF_B2L, n * PB + k, W2[k * 64 + n]);
    }
    for (int i = tid; i < 1024; i += 256) {
        const int n0 = i >> 4, k0 = i & 15;                 // Bt0 [64n][16k]
        put_hl(smc, OFF_B0H, OFF_B0L, n0 * PB0 + k0, (k0 < 9) ? W0[k0 * 64 + n0] : 0.f);
        const int n3 = i >> 6, k3 = i & 63;                 // Bt3 [16n][64k]
        put_hl(smc, OFF_B3H, OFF_B3L, n3 * PB + k3, (n3 < 9) ? W3[k3 * 9 + n3] : 0.f);
    }
    for (int i = tid; i < 208; i += 256) {
        float v = 0.f;
        if (i < 64) v = b0[i];
        else if (i < 128) v = b1[i - 64];
        else if (i < 192) v = b2[i - 128];
        else if (i < 201) v = b3[i - 192];
        bias[i] = v;
    }
    __syncthreads();

    // ---- Per-warp 16-row tile ----
    const int tile = blockIdx.x * 8 + wid;
    const size_t r0 = (size_t)tile * 16;

    // Stage input rows as bf16 hi/lo 16x16 tile (k padded with zeros)
    const uint32_t stoff = (uint32_t)wid * 512;
    if (lane < 16) {
        const float* src = g_cov + (r0 + lane) * 9;
        float x[10];
        #pragma unroll
        for (int q = 0; q < 9; q++) x[q] = src[q];
        x[9] = 0.f;
        uint32_t* ph = (uint32_t*)(smc + OFF_AH + stoff + lane * 32);
        uint32_t* pl = (uint32_t*)(smc + OFF_AL + stoff + lane * 32);
        #pragma unroll
        for (int cq = 0; cq < 5; cq++) {
            uint32_t h, l;
            split2(x[2 * cq], x[2 * cq + 1], h, l);
            ph[cq] = h; pl[cq] = l;
        }
        #pragma unroll
        for (int cq = 5; cq < 8; cq++) { ph[cq] = 0u; pl[cq] = 0u; }
    }
    __syncwarp();

    uint32_t A0h[4], A0l[4];
    {
        const uint32_t aaddr = sb + OFF_AH + stoff + (lane & 15) * 32 + ((lane >> 4) << 4);
        ldsm4(A0h, aaddr);
        ldsm4(A0l, aaddr + (OFF_AL - OFF_AH));
    }

    float d[32];
    #pragma unroll
    for (int j = 0; j < 32; j++) d[j] = 0.f;

    // ---- Layer 0: K=16 (9 real), N=64 ----
    {
        const int n    = (lane & 7) + ((lane >> 4) << 3);
        const int koff = ((lane >> 3) & 1) * 8;
        #pragma unroll
        for (int ntp = 0; ntp < 4; ntp++) {
            const uint32_t ba = sb + ((n + ntp * 16) * PB0 + koff) * 2;
            uint32_t bh[4], bl[4];
            ldsm4(bh, ba + OFF_B0H);
            ldsm4(bl, ba + OFF_B0L);
            float* dp = d + ntp * 8;
            mma_bf16(dp, A0h, bh[0], bh[1]);
            mma_bf16(dp, A0h, bl[0], bl[1]);
            mma_bf16(dp, A0l, bh[0], bh[1]);
            mma_bf16(dp + 4, A0h, bh[2], bh[3]);
            mma_bf16(dp + 4, A0h, bl[2], bl[3]);
            mma_bf16(dp + 4, A0l, bh[2], bh[3]);
        }
    }

    uint32_t AH[16], AL[16];

    // ---- Layers 1,2 (hidden 64->64) ----
    epi_repack(d, bias + 0, AH, AL, lane);
    #pragma unroll
    for (int j = 0; j < 32; j++) d[j] = 0.f;
    hidden_layer(d, AH, AL, sb, OFF_B1H, OFF_B1L, lane);

    epi_repack(d, bias + 64, AH, AL, lane);
    #pragma unroll
    for (int j = 0; j < 32; j++) d[j] = 0.f;
    hidden_layer(d, AH, AL, sb, OFF_B2H, OFF_B2L, lane);

    epi_repack(d, bias + 128, AH, AL, lane);

    // ---- Layer 3: K=64, N=16 (9 real) ----
    float e[8];
    #pragma unroll
    for (int j = 0; j < 8; j++) e[j] = 0.f;
    {
        const int n    = (lane & 7) + ((lane >> 4) << 3);
        const int koff = ((lane >> 3) & 1) * 8;
        #pragma unroll
        for (int s = 0; s < 4; s++) {
            const uint32_t ba = sb + (n * PB + 16 * s + koff) * 2;
            uint32_t bh[4], bl[4];
            ldsm4(bh, ba + OFF_B3H);
            ldsm4(bl, ba + OFF_B3L);
            const uint32_t* ah = AH + 4 * s;
            const uint32_t* al = AL + 4 * s;
            mma_bf16(e, ah, bh[0], bh[1]);
            mma_bf16(e, ah, bl[0], bl[1]);
            mma_bf16(e, al, bh[0], bh[1]);
            mma_bf16(e + 4, ah, bh[2], bh[3]);
            mma_bf16(e + 4, ah, bl[2], bl[3]);
            mma_bf16(e + 4, al, bh[2], bh[3]);
        }
    }

    // ---- Final bias + accurate ELU + store ----
    {
        const int row = lane >> 2;
        const int c0  = (lane & 3) * 2;
        float* o0 = out + (r0 + row) * 9;
        float* o1 = out + (r0 + row + 8) * 9;
        const float bc0 = bias[192 + c0];
        const float bc1 = bias[192 + c0 + 1];
        float t;
        t = e[0] + bc0; o0[c0]     = t > 0.f ? t : expm1f(t);
        t = e[1] + bc1; o0[c0 + 1] = t > 0.f ? t : expm1f(t);
        t = e[2] + bc0; o1[c0]     = t > 0.f ? t : expm1f(t);
        t = e[3] + bc1; o1[c0 + 1] = t > 0.f ? t : expm1f(t);
        if ((lane & 3) == 0) {
            const float b8 = bias[200];
            t = e[4] + b8; o0[8] = t > 0.f ? t : expm1f(t);
            t = e[6] + b8; o1[8] = t > 0.f ? t : expm1f(t);
        }
    }
}

// ---------------------------------------------------------------------------
// Launch
// ---------------------------------------------------------------------------
extern "C" void kernel_launch(void* const* d_in, const int* in_sizes, int n_in,
                              void* d_out, int out_size)
{
    const float* coords = (const float*)d_in[0];
    const float* distsq = (const float*)d_in[1];
    const float* feats  = (const float*)d_in[2];
    const int*   nidx   = (const int*)  d_in[3];
    const float* W0 = (const float*)d_in[4];
    const float* b0 = (const float*)d_in[5];
    const float* W1 = (const float*)d_in[6];
    const float* b1 = (const float*)d_in[7];
    const float* W2 = (const float*)d_in[8];
    const float* b2 = (const float*)d_in[9];
    const float* W3 = (const float*)d_in[10];
    const float* b3 = (const float*)d_in[11];
    float* out = (float*)d_out;

    cov_kernel<<<Vn / VPB, 128>>>(coords, distsq, feats, nidx);

    cudaFuncSetAttribute(mlp_kernel,
                         cudaFuncAttributeMaxDynamicSharedMemorySize, MLP_SMEM);
    // 100,000 tiles of 16 rows; 8 warps (tiles) per block
    mlp_kernel<<<12500, 256, MLP_SMEM>>>(W0, b0, W1, b1, W2, b2, W3, b3, out);
}